// round 2
// baseline (speedup 1.0000x reference)
#include <cuda_runtime.h>
#include <cstdint>

#define NN 100000
#define FIN 128
#define FH 128
#define FO 64

// ---------------- scratch (device globals; no allocation allowed) ----------
__device__ float g_dinv[NN];                       // deg -> rsqrt(deg)
__device__ float g_h1[(size_t)NN * FH];            // x @ W1
__device__ float g_a1[(size_t)NN * FH];            // aggregated + relu
__device__ float g_h2[(size_t)NN * FO];            // a1 @ W2
__device__ int   g_is64;                           // edge_index dtype flag

// ---------------- dtype detection -----------------------------------------
// If edge_index is int64, every odd 32-bit word is a high word == 0
// (indices are in [0, 1e5)). If int32, odd words are random node indices
// (P(all zero) ~ 0). Deterministic, runs every launch.
__global__ void detect_dtype_kernel(const unsigned int* __restrict__ w) {
    if (blockIdx.x == 0 && threadIdx.x == 0) {
        unsigned int acc = 0;
        for (int i = 1; i < 2048; i += 2) acc |= w[i];
        g_is64 = (acc == 0u) ? 1 : 0;
    }
}

__device__ __forceinline__ void edge_ld(const void* ei, int E, int e, int& s, int& d) {
    if (g_is64) {
        const long long* p = (const long long*)ei;
        s = (int)p[e]; d = (int)p[(size_t)E + e];
    } else {
        const int* p = (const int*)ei;
        s = p[e]; d = p[(size_t)E + e];
    }
}

// ---------------- degree / dinv --------------------------------------------
__global__ void deg_init_kernel(int n) {
    int i = blockIdx.x * blockDim.x + threadIdx.x;
    if (i < n) g_dinv[i] = 1.0f;   // self-loop contributes 1
}

__global__ void deg_scatter_kernel(const void* __restrict__ ei, int E) {
    int e = blockIdx.x * blockDim.x + threadIdx.x;
    if (e >= E) return;
    int s, d; edge_ld(ei, E, e, s, d);
    atomicAdd(&g_dinv[d], 1.0f);
}

__global__ void dinv_kernel(int n) {
    int i = blockIdx.x * blockDim.x + threadIdx.x;
    if (i < n) g_dinv[i] = rsqrtf(g_dinv[i]);
}

// ---------------- GEMM: H = X[ n x 128 ] @ W[128 x 128] --------------------
// 128 threads/block, 16 rows/block, K staged in 32-chunks through smem.
__global__ void gemm128_kernel(const float* __restrict__ X,
                               const float* __restrict__ W,
                               float* __restrict__ H, int n) {
    __shared__ float Ws[32][128];
    __shared__ float xs[16][32];
    const int tid = threadIdx.x;
    const int row0 = blockIdx.x * 16;
    float acc[16];
#pragma unroll
    for (int r = 0; r < 16; r++) acc[r] = 0.0f;

    for (int k0 = 0; k0 < 128; k0 += 32) {
#pragma unroll
        for (int i = tid; i < 32 * 128; i += 128)
            Ws[i >> 7][i & 127] = W[(size_t)(k0 + (i >> 7)) * 128 + (i & 127)];
#pragma unroll
        for (int i = tid; i < 16 * 32; i += 128) {
            int r = i >> 5, k = i & 31;
            int gr = row0 + r;
            xs[r][k] = (gr < n) ? X[(size_t)gr * 128 + k0 + k] : 0.0f;
        }
        __syncthreads();
#pragma unroll
        for (int k = 0; k < 32; k++) {
            float w = Ws[k][tid];
#pragma unroll
            for (int r = 0; r < 16; r++) acc[r] += xs[r][k] * w;
        }
        __syncthreads();
    }
#pragma unroll
    for (int r = 0; r < 16; r++) {
        int gr = row0 + r;
        if (gr < n) H[(size_t)gr * 128 + tid] = acc[r];
    }
}

// ---------------- GEMM: H = A[ n x 128 ] @ W[128 x 64] ---------------------
// 128 threads: tid -> (half = tid>>6 picks 8 rows, j = tid&63 picks column).
__global__ void gemm64_kernel(const float* __restrict__ A,
                              const float* __restrict__ W,
                              float* __restrict__ H, int n) {
    __shared__ float Ws[32][64];
    __shared__ float xs[16][32];
    const int tid = threadIdx.x;
    const int j = tid & 63;
    const int half = tid >> 6;
    const int row0 = blockIdx.x * 16;
    float acc[8];
#pragma unroll
    for (int r = 0; r < 8; r++) acc[r] = 0.0f;

    for (int k0 = 0; k0 < 128; k0 += 32) {
#pragma unroll
        for (int i = tid; i < 32 * 64; i += 128)
            Ws[i >> 6][i & 63] = W[(size_t)(k0 + (i >> 6)) * 64 + (i & 63)];
#pragma unroll
        for (int i = tid; i < 16 * 32; i += 128) {
            int r = i >> 5, k = i & 31;
            int gr = row0 + r;
            xs[r][k] = (gr < n) ? A[(size_t)gr * 128 + k0 + k] : 0.0f;
        }
        __syncthreads();
#pragma unroll
        for (int k = 0; k < 32; k++) {
            float w = Ws[k][j];
#pragma unroll
            for (int r = 0; r < 8; r++) acc[r] += xs[half * 8 + r][k] * w;
        }
        __syncthreads();
    }
#pragma unroll
    for (int r = 0; r < 8; r++) {
        int gr = row0 + half * 8 + r;
        if (gr < n) H[(size_t)gr * 64 + j] = acc[r];
    }
}

// ---------------- aggregation ----------------------------------------------
// out[i] = h[i] * dinv[i]^2   (self-loop term; also initializes the buffer)
__global__ void self_init_kernel(const float4* __restrict__ h,
                                 float4* __restrict__ out, int n, int f4) {
    int idx = blockIdx.x * blockDim.x + threadIdx.x;
    if (idx >= n * f4) return;
    int row = idx / f4;
    float di = g_dinv[row];
    float s = di * di;
    float4 v = h[idx];
    v.x *= s; v.y *= s; v.z *= s; v.w *= s;
    out[idx] = v;
}

__device__ __forceinline__ void red_add_v4(float* p, float a, float b, float c, float d) {
    asm volatile("red.global.add.v4.f32 [%0], {%1,%2,%3,%4};"
                 :: "l"(p), "f"(a), "f"(b), "f"(c), "f"(d) : "memory");
}

// F=128: one warp per edge; lane handles one float4 chunk of the row.
__global__ void scatter128_kernel(const void* __restrict__ ei, int E,
                                  const float4* __restrict__ h,
                                  float* __restrict__ out) {
    int gid = blockIdx.x * blockDim.x + threadIdx.x;
    int e = gid >> 5, lane = gid & 31;
    if (e >= E) return;
    int s, d; edge_ld(ei, E, e, s, d);        // same addr within warp -> broadcast
    float w = g_dinv[s] * g_dinv[d];
    float4 v = h[(size_t)s * 32 + lane];
    float* p = out + (size_t)d * 128 + lane * 4;
    red_add_v4(p, v.x * w, v.y * w, v.z * w, v.w * w);
}

// F=64: 16 threads per edge.
__global__ void scatter64_kernel(const void* __restrict__ ei, int E,
                                 const float4* __restrict__ h,
                                 float* __restrict__ out) {
    int gid = blockIdx.x * blockDim.x + threadIdx.x;
    int e = gid >> 4, c = gid & 15;
    if (e >= E) return;
    int s, d; edge_ld(ei, E, e, s, d);
    float w = g_dinv[s] * g_dinv[d];
    float4 v = h[(size_t)s * 16 + c];
    float* p = out + (size_t)d * 64 + c * 4;
    red_add_v4(p, v.x * w, v.y * w, v.z * w, v.w * w);
}

// a = relu(a + b1)
__global__ void relu_bias_kernel(float4* __restrict__ a,
                                 const float4* __restrict__ b, int n) {
    int idx = blockIdx.x * blockDim.x + threadIdx.x;
    if (idx >= n * 32) return;
    float4 bv = b[idx & 31];
    float4 v = a[idx];
    v.x = fmaxf(v.x + bv.x, 0.0f);
    v.y = fmaxf(v.y + bv.y, 0.0f);
    v.z = fmaxf(v.z + bv.z, 0.0f);
    v.w = fmaxf(v.w + bv.w, 0.0f);
    a[idx] = v;
}

// out += b2
__global__ void bias_out_kernel(float4* __restrict__ o,
                                const float4* __restrict__ b, int n) {
    int idx = blockIdx.x * blockDim.x + threadIdx.x;
    if (idx >= n * 16) return;
    float4 bv = b[idx & 15];
    float4 v = o[idx];
    v.x += bv.x; v.y += bv.y; v.z += bv.z; v.w += bv.w;
    o[idx] = v;
}

// ---------------- launch ----------------------------------------------------
extern "C" void kernel_launch(void* const* d_in, const int* in_sizes, int n_in,
                              void* d_out, int out_size) {
    const float* x  = (const float*)d_in[0];
    const void*  ei = d_in[1];
    const float* W1 = (const float*)d_in[2];
    const float* b1 = (const float*)d_in[3];
    const float* W2 = (const float*)d_in[4];
    const float* b2 = (const float*)d_in[5];
    float* out = (float*)d_out;

    const int n = in_sizes[0] / FIN;      // 100000
    const int E = in_sizes[1] / 2;        // 600000 (element count same for i32/i64)

    float *p_dinv_unused, *p_h1, *p_a1, *p_h2;
    cudaGetSymbolAddress((void**)&p_dinv_unused, g_dinv);
    cudaGetSymbolAddress((void**)&p_h1, g_h1);
    cudaGetSymbolAddress((void**)&p_a1, g_a1);
    cudaGetSymbolAddress((void**)&p_h2, g_h2);

    // dtype + normalization (graph-invariant across both layers)
    detect_dtype_kernel<<<1, 32>>>((const unsigned int*)ei);
    deg_init_kernel<<<(n + 255) / 256, 256>>>(n);
    deg_scatter_kernel<<<(E + 255) / 256, 256>>>(ei, E);
    dinv_kernel<<<(n + 255) / 256, 256>>>(n);

    // layer 1
    gemm128_kernel<<<(n + 15) / 16, 128>>>(x, W1, p_h1, n);
    self_init_kernel<<<(n * 32 + 255) / 256, 256>>>((const float4*)p_h1,
                                                    (float4*)p_a1, n, 32);
    scatter128_kernel<<<(int)(((size_t)E * 32 + 255) / 256), 256>>>(
        ei, E, (const float4*)p_h1, p_a1);
    relu_bias_kernel<<<(n * 32 + 255) / 256, 256>>>((float4*)p_a1,
                                                    (const float4*)b1, n);

    // layer 2
    gemm64_kernel<<<(n + 15) / 16, 128>>>(p_a1, W2, p_h2, n);
    self_init_kernel<<<(n * 16 + 255) / 256, 256>>>((const float4*)p_h2,
                                                    (float4*)out, n, 16);
    scatter64_kernel<<<(int)(((size_t)E * 16 + 255) / 256), 256>>>(
        ei, E, (const float4*)p_h2, out);
    bias_out_kernel<<<(n * 16 + 255) / 256, 256>>>((float4*)out,
                                                   (const float4*)b2, n);
}

// round 3
// speedup vs baseline: 1.2246x; 1.2246x over previous
#include <cuda_runtime.h>
#include <cstdint>

#define NN 100000
#define FIN 128
#define FH 128
#define FO 64
#define EMAX 600000

// ---------------- scratch (device globals; no allocation allowed) ----------
__device__ float g_dinv[NN];
__device__ float g_h1[(size_t)NN * FH];            // x @ W1
__device__ float g_a1[(size_t)NN * FH];            // aggregated + relu
__device__ float g_h2[(size_t)NN * FO];            // a1 @ W2
__device__ int   g_cnt[NN];                        // in-degree (no self loop)
__device__ int   g_start[NN];                      // CSR row start (scrambled order)
__device__ int   g_woff[NN];                       // fill cursor per row
__device__ int   g_csrc[EMAX];                     // CSR src node per slot
__device__ float g_cw[EMAX];                       // CSR edge weight dinv[s]*dinv[d]
__device__ int   g_cursor;
__device__ int   g_is64;

// ---------------- dtype detection -----------------------------------------
__global__ void detect_dtype_kernel(const unsigned int* __restrict__ w) {
    if (blockIdx.x == 0 && threadIdx.x == 0) {
        unsigned int acc = 0;
        for (int i = 1; i < 2048; i += 2) acc |= w[i];
        g_is64 = (acc == 0u) ? 1 : 0;
    }
}

__device__ __forceinline__ void edge_ld(const void* ei, int E, int e, int& s, int& d) {
    if (g_is64) {
        const long long* p = (const long long*)ei;
        s = (int)p[e]; d = (int)p[(size_t)E + e];
    } else {
        const int* p = (const int*)ei;
        s = p[e]; d = p[(size_t)E + e];
    }
}

// ---------------- CSR build -------------------------------------------------
__global__ void init_kernel(int n) {
    int i = blockIdx.x * blockDim.x + threadIdx.x;
    if (i < n) g_cnt[i] = 0;
    if (i == 0) g_cursor = 0;
}

__global__ void count_kernel(const void* __restrict__ ei, int E) {
    int e = blockIdx.x * blockDim.x + threadIdx.x;
    if (e >= E) return;
    int s, d; edge_ld(ei, E, e, s, d);
    atomicAdd(&g_cnt[d], 1);
}

// dinv = rsqrt(deg+1); allocate a contiguous CSR slab per row via atomic cursor.
__global__ void prep_kernel(int n) {
    int i = blockIdx.x * blockDim.x + threadIdx.x;
    if (i >= n) return;
    int c = g_cnt[i];
    g_dinv[i] = rsqrtf((float)(c + 1));
    int st = atomicAdd(&g_cursor, c);
    g_start[i] = st;
    g_woff[i]  = st;
}

__global__ void fill_kernel(const void* __restrict__ ei, int E) {
    int e = blockIdx.x * blockDim.x + threadIdx.x;
    if (e >= E) return;
    int s, d; edge_ld(ei, E, e, s, d);
    int pos = atomicAdd(&g_woff[d], 1);
    g_csrc[pos] = s;
    g_cw[pos]   = g_dinv[s] * g_dinv[d];
}

// ---------------- GEMM: H = X[n x 128] @ W[128 x 128] ----------------------
// 128 threads/block, 16 rows/block. W column in registers, xs via LDS.128.
__global__ void gemm128_kernel(const float* __restrict__ X,
                               const float* __restrict__ W,
                               float* __restrict__ H, int n) {
    __shared__ float Ws[32][128];
    __shared__ float xs[16][32];
    const int tid = threadIdx.x;
    const int row0 = blockIdx.x * 16;
    float acc[16];
#pragma unroll
    for (int r = 0; r < 16; r++) acc[r] = 0.0f;

    for (int k0 = 0; k0 < 128; k0 += 32) {
#pragma unroll
        for (int i = tid; i < 32 * 128; i += 128)
            Ws[i >> 7][i & 127] = W[(size_t)(k0 + (i >> 7)) * 128 + (i & 127)];
#pragma unroll
        for (int i = tid; i < 16 * 32; i += 128) {
            int r = i >> 5, k = i & 31;
            int gr = row0 + r;
            xs[r][k] = (gr < n) ? X[(size_t)gr * 128 + k0 + k] : 0.0f;
        }
        __syncthreads();
        float wreg[32];
#pragma unroll
        for (int k = 0; k < 32; k++) wreg[k] = Ws[k][tid];
#pragma unroll
        for (int r = 0; r < 16; r++) {
#pragma unroll
            for (int k = 0; k < 32; k++) acc[r] += xs[r][k] * wreg[k];
        }
        __syncthreads();
    }
#pragma unroll
    for (int r = 0; r < 16; r++) {
        int gr = row0 + r;
        if (gr < n) H[(size_t)gr * 128 + tid] = acc[r];
    }
}

// ---------------- GEMM: H = A[n x 128] @ W[128 x 64] -----------------------
__global__ void gemm64_kernel(const float* __restrict__ A,
                              const float* __restrict__ W,
                              float* __restrict__ H, int n) {
    __shared__ float Ws[32][64];
    __shared__ float xs[16][32];
    const int tid = threadIdx.x;
    const int j = tid & 63;
    const int half = tid >> 6;
    const int row0 = blockIdx.x * 16;
    float acc[8];
#pragma unroll
    for (int r = 0; r < 8; r++) acc[r] = 0.0f;

    for (int k0 = 0; k0 < 128; k0 += 32) {
#pragma unroll
        for (int i = tid; i < 32 * 64; i += 128)
            Ws[i >> 6][i & 63] = W[(size_t)(k0 + (i >> 6)) * 64 + (i & 63)];
#pragma unroll
        for (int i = tid; i < 16 * 32; i += 128) {
            int r = i >> 5, k = i & 31;
            int gr = row0 + r;
            xs[r][k] = (gr < n) ? A[(size_t)gr * 128 + k0 + k] : 0.0f;
        }
        __syncthreads();
        float wreg[32];
#pragma unroll
        for (int k = 0; k < 32; k++) wreg[k] = Ws[k][j];
#pragma unroll
        for (int r = 0; r < 8; r++) {
#pragma unroll
            for (int k = 0; k < 32; k++)
                acc[r] += xs[half * 8 + r][k] * wreg[k];
        }
        __syncthreads();
    }
#pragma unroll
    for (int r = 0; r < 8; r++) {
        int gr = row0 + half * 8 + r;
        if (gr < n) H[(size_t)gr * 64 + j] = acc[r];
    }
}

// ---------------- gather aggregation (no atomics) ---------------------------
// F=128: one warp per node; lane owns one float4 column chunk.
// out[i] = act( b + dinv[i]^2 * h[i] + sum_j w_j * h[src_j] )
__global__ void agg128_kernel(const float4* __restrict__ h,
                              const float4* __restrict__ bias,
                              float4* __restrict__ out, int n, int relu) {
    int gid = blockIdx.x * blockDim.x + threadIdx.x;
    int node = gid >> 5, lane = gid & 31;
    if (node >= n) return;
    float di = g_dinv[node];
    float s2 = di * di;
    float4 v = h[(size_t)node * 32 + lane];
    float4 acc;
    acc.x = v.x * s2; acc.y = v.y * s2; acc.z = v.z * s2; acc.w = v.w * s2;
    int b = g_start[node];
    int e = b + g_cnt[node];
    for (int j = b; j < e; j++) {
        int   s = g_csrc[j];          // broadcast within warp
        float w = g_cw[j];
        float4 u = h[(size_t)s * 32 + lane];
        acc.x += u.x * w; acc.y += u.y * w; acc.z += u.z * w; acc.w += u.w * w;
    }
    float4 bv = bias[lane];
    acc.x += bv.x; acc.y += bv.y; acc.z += bv.z; acc.w += bv.w;
    if (relu) {
        acc.x = fmaxf(acc.x, 0.0f); acc.y = fmaxf(acc.y, 0.0f);
        acc.z = fmaxf(acc.z, 0.0f); acc.w = fmaxf(acc.w, 0.0f);
    }
    out[(size_t)node * 32 + lane] = acc;
}

// F=64: one warp per node; lane owns one float2 column chunk.
__global__ void agg64_kernel(const float2* __restrict__ h,
                             const float2* __restrict__ bias,
                             float2* __restrict__ out, int n) {
    int gid = blockIdx.x * blockDim.x + threadIdx.x;
    int node = gid >> 5, lane = gid & 31;
    if (node >= n) return;
    float di = g_dinv[node];
    float s2 = di * di;
    float2 v = h[(size_t)node * 32 + lane];
    float2 acc;
    acc.x = v.x * s2; acc.y = v.y * s2;
    int b = g_start[node];
    int e = b + g_cnt[node];
    for (int j = b; j < e; j++) {
        int   s = g_csrc[j];
        float w = g_cw[j];
        float2 u = h[(size_t)s * 32 + lane];
        acc.x += u.x * w; acc.y += u.y * w;
    }
    float2 bv = bias[lane];
    acc.x += bv.x; acc.y += bv.y;
    out[(size_t)node * 32 + lane] = acc;
}

// ---------------- launch ----------------------------------------------------
extern "C" void kernel_launch(void* const* d_in, const int* in_sizes, int n_in,
                              void* d_out, int out_size) {
    const float* x  = (const float*)d_in[0];
    const void*  ei = d_in[1];
    const float* W1 = (const float*)d_in[2];
    const float* b1 = (const float*)d_in[3];
    const float* W2 = (const float*)d_in[4];
    const float* b2 = (const float*)d_in[5];
    float* out = (float*)d_out;

    const int n = in_sizes[0] / FIN;      // 100000
    const int E = in_sizes[1] / 2;        // 600000

    float *p_h1, *p_a1, *p_h2;
    cudaGetSymbolAddress((void**)&p_h1, g_h1);
    cudaGetSymbolAddress((void**)&p_a1, g_a1);
    cudaGetSymbolAddress((void**)&p_h2, g_h2);

    // CSR build (shared by both layers)
    detect_dtype_kernel<<<1, 32>>>((const unsigned int*)ei);
    init_kernel<<<(n + 255) / 256, 256>>>(n);
    count_kernel<<<(E + 255) / 256, 256>>>(ei, E);
    prep_kernel<<<(n + 255) / 256, 256>>>(n);
    fill_kernel<<<(E + 255) / 256, 256>>>(ei, E);

    // layer 1: h1 = x@W1 ; a1 = relu(Agg(h1) + b1)
    gemm128_kernel<<<(n + 15) / 16, 128>>>(x, W1, p_h1, n);
    agg128_kernel<<<(n * 32 + 255) / 256, 256>>>(
        (const float4*)p_h1, (const float4*)b1, (float4*)p_a1, n, 1);

    // layer 2: h2 = a1@W2 ; out = Agg(h2) + b2
    gemm64_kernel<<<(n + 15) / 16, 128>>>(p_a1, W2, p_h2, n);
    agg64_kernel<<<(n * 32 + 255) / 256, 256>>>(
        (const float2*)p_h2, (const float2*)b2, (float2*)out, n);
}

// round 5
// speedup vs baseline: 1.7051x; 1.3924x over previous
#include <cuda_runtime.h>
#include <cuda_bf16.h>
#include <cstdint>

#define NN 100000
#define FIN 128
#define FH 128
#define FO 64
#define EMAX 600000

// ---------------- scratch (device globals) ----------------------------------
__device__ float g_dinv[NN];
__device__ float g_h1[(size_t)NN * FH];              // layer1 GEMM out (fp32)
__device__ float g_h2[(size_t)NN * FO];              // layer2 GEMM out (fp32)
__device__ __nv_bfloat16 g_xhi[(size_t)NN * FIN];    // split input X
__device__ __nv_bfloat16 g_xlo[(size_t)NN * FIN];
__device__ __nv_bfloat16 g_a1hi[(size_t)NN * FH];    // split layer1 activation
__device__ __nv_bfloat16 g_a1lo[(size_t)NN * FH];
__device__ __nv_bfloat16 g_w1thi[FH * FIN];          // W1^T [feat][k]
__device__ __nv_bfloat16 g_w1tlo[FH * FIN];
__device__ __nv_bfloat16 g_w2thi[FO * FH];           // W2^T [feat][k]
__device__ __nv_bfloat16 g_w2tlo[FO * FH];
__device__ int   g_cnt[NN];
__device__ int   g_start[NN];
__device__ int   g_woff[NN];
__device__ int   g_csrc[EMAX];
__device__ float g_cw[EMAX];
__device__ int   g_cursor;
__device__ int   g_is64;

// ---------------- dtype detection ------------------------------------------
__global__ void detect_dtype_kernel(const unsigned int* __restrict__ w) {
    if (blockIdx.x == 0 && threadIdx.x == 0) {
        unsigned int acc = 0;
        for (int i = 1; i < 2048; i += 2) acc |= w[i];
        g_is64 = (acc == 0u) ? 1 : 0;
    }
}

__device__ __forceinline__ void edge_ld(const void* ei, int E, int e, int& s, int& d) {
    if (g_is64) {
        const long long* p = (const long long*)ei;
        s = (int)p[e]; d = (int)p[(size_t)E + e];
    } else {
        const int* p = (const int*)ei;
        s = p[e]; d = p[(size_t)E + e];
    }
}

// ---------------- CSR build --------------------------------------------------
__global__ void init_kernel(int n) {
    int i = blockIdx.x * blockDim.x + threadIdx.x;
    if (i < n) g_cnt[i] = 0;
    if (i == 0) g_cursor = 0;
}
__global__ void count_kernel(const void* __restrict__ ei, int E) {
    int e = blockIdx.x * blockDim.x + threadIdx.x;
    if (e >= E) return;
    int s, d; edge_ld(ei, E, e, s, d);
    atomicAdd(&g_cnt[d], 1);
}
__global__ void prep_kernel(int n) {
    int i = blockIdx.x * blockDim.x + threadIdx.x;
    if (i >= n) return;
    int c = g_cnt[i];
    g_dinv[i] = rsqrtf((float)(c + 1));
    int st = atomicAdd(&g_cursor, c);
    g_start[i] = st;
    g_woff[i]  = st;
}
__global__ void fill_kernel(const void* __restrict__ ei, int E) {
    int e = blockIdx.x * blockDim.x + threadIdx.x;
    if (e >= E) return;
    int s, d; edge_ld(ei, E, e, s, d);
    int pos = atomicAdd(&g_woff[d], 1);
    g_csrc[pos] = s;
    g_cw[pos]   = g_dinv[s] * g_dinv[d];
}

// ---------------- conversions ------------------------------------------------
__device__ __forceinline__ void split_bf16(float v, __nv_bfloat16& h, __nv_bfloat16& l) {
    h = __float2bfloat16(v);
    l = __float2bfloat16(v - __bfloat162float(h));
}

__global__ void convert_x_kernel(const float2* __restrict__ x,
                                 __nv_bfloat162* __restrict__ hi,
                                 __nv_bfloat162* __restrict__ lo, int n2) {
    int i = blockIdx.x * blockDim.x + threadIdx.x;
    if (i >= n2) return;
    float2 v = x[i];
    __nv_bfloat162 H, L;
    split_bf16(v.x, H.x, L.x);
    split_bf16(v.y, H.y, L.y);
    hi[i] = H; lo[i] = L;
}

// W1[k][n] (128x128) -> w1t[f][k]; W2[k][n] (128x64) -> w2t[f][k]
__global__ void convert_w_kernel(const float* __restrict__ W1,
                                 const float* __restrict__ W2) {
    int stride = gridDim.x * blockDim.x;
    for (int i = blockIdx.x * blockDim.x + threadIdx.x; i < FH * FIN; i += stride) {
        int f = i >> 7, k = i & 127;
        split_bf16(W1[(size_t)k * FH + f], g_w1thi[i], g_w1tlo[i]);
    }
    for (int i = blockIdx.x * blockDim.x + threadIdx.x; i < FO * FH; i += stride) {
        int f = i >> 7, k = i & 127;
        split_bf16(W2[(size_t)k * FO + f], g_w2thi[i], g_w2tlo[i]);
    }
}

// ---------------- bf16-split tensor-core GEMM --------------------------------
// H[node][f] = sum_k X[node][k] * Wt[f][k]. A = Wt (row-major m16k16),
// B = X (col-major n8k16, n = node). 3-term split: AhiBhi + AhiBlo + AloBhi.
__device__ __forceinline__ void mma16816(float* c, const unsigned* a,
                                         unsigned b0, unsigned b1) {
    asm volatile(
        "mma.sync.aligned.m16n8k16.row.col.f32.bf16.bf16.f32 "
        "{%0,%1,%2,%3}, {%4,%5,%6,%7}, {%8,%9}, {%0,%1,%2,%3};"
        : "+f"(c[0]), "+f"(c[1]), "+f"(c[2]), "+f"(c[3])
        : "r"(a[0]), "r"(a[1]), "r"(a[2]), "r"(a[3]), "r"(b0), "r"(b1));
}

template <int NF, int TPB>   // NF: output features (warps = NF/16); TPB: node tiles per block
__global__ void gemm_bf16_kernel(const __nv_bfloat16* __restrict__ xhi,
                                 const __nv_bfloat16* __restrict__ xlo,
                                 const __nv_bfloat16* __restrict__ wthi,
                                 const __nv_bfloat16* __restrict__ wtlo,
                                 float* __restrict__ H, int n) {
    const int warp = threadIdx.x >> 5, lane = threadIdx.x & 31;
    const int g = lane >> 2, tg = lane & 3;
    const int f0 = warp * 16;

    // Preload full-K weight fragments (loop-invariant).
    unsigned ahi[8][4], alo[8][4];
#pragma unroll
    for (int ks = 0; ks < 8; ks++) {
        int k0 = ks * 16 + tg * 2;
        ahi[ks][0] = *(const unsigned*)(wthi + (size_t)(f0 + g) * 128 + k0);
        ahi[ks][1] = *(const unsigned*)(wthi + (size_t)(f0 + 8 + g) * 128 + k0);
        ahi[ks][2] = *(const unsigned*)(wthi + (size_t)(f0 + g) * 128 + k0 + 8);
        ahi[ks][3] = *(const unsigned*)(wthi + (size_t)(f0 + 8 + g) * 128 + k0 + 8);
        alo[ks][0] = *(const unsigned*)(wtlo + (size_t)(f0 + g) * 128 + k0);
        alo[ks][1] = *(const unsigned*)(wtlo + (size_t)(f0 + 8 + g) * 128 + k0);
        alo[ks][2] = *(const unsigned*)(wtlo + (size_t)(f0 + g) * 128 + k0 + 8);
        alo[ks][3] = *(const unsigned*)(wtlo + (size_t)(f0 + 8 + g) * 128 + k0 + 8);
    }

    const int tile0 = blockIdx.x * TPB;
#pragma unroll 1
    for (int t = 0; t < TPB; t++) {
        int n0 = (tile0 + t) * 8;
        if (n0 >= n) break;
        int node = n0 + g;
        bool v = node < n;
        const unsigned* xh = (const unsigned*)(xhi + (size_t)node * 128);
        const unsigned* xl = (const unsigned*)(xlo + (size_t)node * 128);
        float c[4] = {0.f, 0.f, 0.f, 0.f};
#pragma unroll
        for (int ks = 0; ks < 8; ks++) {
            unsigned bh0 = v ? xh[ks * 8 + tg]     : 0u;
            unsigned bh1 = v ? xh[ks * 8 + 4 + tg] : 0u;
            unsigned bl0 = v ? xl[ks * 8 + tg]     : 0u;
            unsigned bl1 = v ? xl[ks * 8 + 4 + tg] : 0u;
            mma16816(c, ahi[ks], bh0, bh1);
            mma16816(c, ahi[ks], bl0, bl1);
            mma16816(c, alo[ks], bh0, bh1);
        }
        int nc0 = n0 + tg * 2, nc1 = nc0 + 1;
        if (nc0 < n) {
            H[(size_t)nc0 * NF + f0 + g]     = c[0];
            H[(size_t)nc0 * NF + f0 + 8 + g] = c[2];
        }
        if (nc1 < n) {
            H[(size_t)nc1 * NF + f0 + g]     = c[1];
            H[(size_t)nc1 * NF + f0 + 8 + g] = c[3];
        }
    }
}

// ---------------- gather aggregation -----------------------------------------
// Layer 1: out = relu(b + dinv^2*h + sum w*h[src]); writes bf16 hi/lo split.
__global__ void agg128_kernel(const float4* __restrict__ h,
                              const float4* __restrict__ bias,
                              __nv_bfloat162* __restrict__ ahi,
                              __nv_bfloat162* __restrict__ alo, int n) {
    int gid = blockIdx.x * blockDim.x + threadIdx.x;
    int node = gid >> 5, lane = gid & 31;
    if (node >= n) return;
    float di = g_dinv[node];
    float s2 = di * di;
    float4 v = h[(size_t)node * 32 + lane];
    float4 acc;
    acc.x = v.x * s2; acc.y = v.y * s2; acc.z = v.z * s2; acc.w = v.w * s2;
    int b = g_start[node];
    int e = b + g_cnt[node];
    for (int j = b; j < e; j++) {
        int   s = g_csrc[j];
        float w = g_cw[j];
        float4 u = h[(size_t)s * 32 + lane];
        acc.x += u.x * w; acc.y += u.y * w; acc.z += u.z * w; acc.w += u.w * w;
    }
    float4 bv = bias[lane];
    acc.x = fmaxf(acc.x + bv.x, 0.0f);
    acc.y = fmaxf(acc.y + bv.y, 0.0f);
    acc.z = fmaxf(acc.z + bv.z, 0.0f);
    acc.w = fmaxf(acc.w + bv.w, 0.0f);
    __nv_bfloat162 H0, L0, H1, L1;
    split_bf16(acc.x, H0.x, L0.x);
    split_bf16(acc.y, H0.y, L0.y);
    split_bf16(acc.z, H1.x, L1.x);
    split_bf16(acc.w, H1.y, L1.y);
    size_t o = (size_t)node * 64 + lane * 2;
    ahi[o] = H0; ahi[o + 1] = H1;
    alo[o] = L0; alo[o + 1] = L1;
}

// Layer 2: out = b + dinv^2*h + sum w*h[src]  (fp32 out).
__global__ void agg64_kernel(const float2* __restrict__ h,
                             const float2* __restrict__ bias,
                             float2* __restrict__ out, int n) {
    int gid = blockIdx.x * blockDim.x + threadIdx.x;
    int node = gid >> 5, lane = gid & 31;
    if (node >= n) return;
    float di = g_dinv[node];
    float s2 = di * di;
    float2 v = h[(size_t)node * 32 + lane];
    float2 acc;
    acc.x = v.x * s2; acc.y = v.y * s2;
    int b = g_start[node];
    int e = b + g_cnt[node];
    for (int j = b; j < e; j++) {
        int   s = g_csrc[j];
        float w = g_cw[j];
        float2 u = h[(size_t)s * 32 + lane];
        acc.x += u.x * w; acc.y += u.y * w;
    }
    float2 bv = bias[lane];
    acc.x += bv.x; acc.y += bv.y;
    out[(size_t)node * 32 + lane] = acc;
}

// ---------------- launch ------------------------------------------------------
extern "C" void kernel_launch(void* const* d_in, const int* in_sizes, int n_in,
                              void* d_out, int out_size) {
    const float* x  = (const float*)d_in[0];
    const void*  ei = d_in[1];
    const float* W1 = (const float*)d_in[2];
    const float* b1 = (const float*)d_in[3];
    const float* W2 = (const float*)d_in[4];
    const float* b2 = (const float*)d_in[5];
    float* out = (float*)d_out;

    const int n = in_sizes[0] / FIN;   // 100000
    const int E = in_sizes[1] / 2;     // 600000

    float *p_h1, *p_h2;
    __nv_bfloat16 *p_xhi, *p_xlo, *p_a1hi, *p_a1lo, *p_w1thi, *p_w1tlo, *p_w2thi, *p_w2tlo;
    cudaGetSymbolAddress((void**)&p_h1, g_h1);
    cudaGetSymbolAddress((void**)&p_h2, g_h2);
    cudaGetSymbolAddress((void**)&p_xhi, g_xhi);
    cudaGetSymbolAddress((void**)&p_xlo, g_xlo);
    cudaGetSymbolAddress((void**)&p_a1hi, g_a1hi);
    cudaGetSymbolAddress((void**)&p_a1lo, g_a1lo);
    cudaGetSymbolAddress((void**)&p_w1thi, g_w1thi);
    cudaGetSymbolAddress((void**)&p_w1tlo, g_w1tlo);
    cudaGetSymbolAddress((void**)&p_w2thi, g_w2thi);
    cudaGetSymbolAddress((void**)&p_w2tlo, g_w2tlo);

    static cudaStream_t s2 = nullptr;
    static cudaEvent_t evFork = nullptr, evJoin = nullptr;
    if (!s2) {
        cudaStreamCreate(&s2);
        cudaEventCreateWithFlags(&evFork, cudaEventDisableTiming);
        cudaEventCreateWithFlags(&evJoin, cudaEventDisableTiming);
    }

    // Fork: CSR build on s2 (independent of GEMM branch).
    cudaEventRecord(evFork, 0);
    cudaStreamWaitEvent(s2, evFork, 0);
    detect_dtype_kernel<<<1, 32, 0, s2>>>((const unsigned int*)ei);
    init_kernel<<<(n + 255) / 256, 256, 0, s2>>>(n);
    count_kernel<<<(E + 255) / 256, 256, 0, s2>>>(ei, E);
    prep_kernel<<<(n + 255) / 256, 256, 0, s2>>>(n);
    fill_kernel<<<(E + 255) / 256, 256, 0, s2>>>(ei, E);
    cudaEventRecord(evJoin, s2);

    // Main branch: converts + layer1 GEMM.
    convert_w_kernel<<<96, 256>>>(W1, W2);
    {
        int n2 = n * (FIN / 2);
        convert_x_kernel<<<(n2 + 255) / 256, 256>>>(
            (const float2*)x, (__nv_bfloat162*)p_xhi, (__nv_bfloat162*)p_xlo, n2);
    }
    gemm_bf16_kernel<128, 16><<<(n + 127) / 128, 256>>>(
        p_xhi, p_xlo, p_w1thi, p_w1tlo, p_h1, n);

    // Join: aggregation needs CSR.
    cudaStreamWaitEvent(0, evJoin, 0);
    agg128_kernel<<<(n * 32 + 255) / 256, 256>>>(
        (const float4*)p_h1, (const float4*)b1,
        (__nv_bfloat162*)p_a1hi, (__nv_bfloat162*)p_a1lo, n);

    // Layer 2.
    gemm_bf16_kernel<64, 16><<<(n + 127) / 128, 128>>>(
        p_a1hi, p_a1lo, p_w2thi, p_w2tlo, p_h2, n);
    agg64_kernel<<<(n * 32 + 255) / 256, 256>>>(
        (const float2*)p_h2, (const float2*)b2, (float2*)out, n);
}

// round 8
// speedup vs baseline: 2.2588x; 1.3247x over previous
#include <cuda_runtime.h>
#include <cuda_bf16.h>
#include <cstdint>

#define NN 100000
#define FIN 128
#define FH 128
#define FO 64
#define EMAX 600000

// ---------------- scratch (device globals) ----------------------------------
__device__ float g_dinv[NN];
__device__ float g_h1[(size_t)NN * FH];              // layer1 GEMM out (fp32)
__device__ float g_h2[(size_t)NN * FO];              // layer2 GEMM out (fp32)
__device__ __nv_bfloat16 g_a1hi[(size_t)NN * FH];    // split layer1 activation
__device__ __nv_bfloat16 g_a1lo[(size_t)NN * FH];
__device__ __nv_bfloat16 g_w1thi[FH * FIN];          // W1^T [feat][k]
__device__ __nv_bfloat16 g_w1tlo[FH * FIN];
__device__ __nv_bfloat16 g_w2thi[FO * FH];           // W2^T [feat][k]
__device__ __nv_bfloat16 g_w2tlo[FO * FH];
__device__ int   g_cnt[NN];
__device__ int   g_start[NN];
__device__ int   g_woff[NN];
__device__ int2  g_edge[EMAX];                       // {src, bits(weight)}
__device__ int   g_cursor;
__device__ int   g_is64;

// ---------------- dtype detection ------------------------------------------
__global__ void detect_dtype_kernel(const unsigned int* __restrict__ w) {
    unsigned acc = 0;
    for (int i = 1 + 2 * threadIdx.x; i < 2048; i += 64) acc |= w[i];
    bool any = __any_sync(0xffffffffu, acc != 0u);
    if (threadIdx.x == 0) g_is64 = any ? 0 : 1;
}

__device__ __forceinline__ void edge_ld(const void* ei, int E, int e, int& s, int& d) {
    if (g_is64) {
        const long long* p = (const long long*)ei;
        s = (int)p[e]; d = (int)p[(size_t)E + e];
    } else {
        const int* p = (const int*)ei;
        s = p[e]; d = p[(size_t)E + e];
    }
}

// ---------------- CSR build --------------------------------------------------
__global__ void init_kernel(int n) {
    int i = blockIdx.x * blockDim.x + threadIdx.x;
    if (i < n) g_cnt[i] = 0;
    if (i == 0) g_cursor = 0;
}
__global__ void count_kernel(const void* __restrict__ ei, int E) {
    int e = blockIdx.x * blockDim.x + threadIdx.x;
    if (e >= E) return;
    int s, d; edge_ld(ei, E, e, s, d);
    atomicAdd(&g_cnt[d], 1);
}
__global__ void prep_kernel(int n) {
    int i = blockIdx.x * blockDim.x + threadIdx.x;
    if (i >= n) return;
    int c = g_cnt[i];
    g_dinv[i] = rsqrtf((float)(c + 1));
    int st = atomicAdd(&g_cursor, c);
    g_start[i] = st;
    g_woff[i]  = st;
}
__global__ void fill_kernel(const void* __restrict__ ei, int E) {
    int e = blockIdx.x * blockDim.x + threadIdx.x;
    if (e >= E) return;
    int s, d; edge_ld(ei, E, e, s, d);
    int pos = atomicAdd(&g_woff[d], 1);
    g_edge[pos] = make_int2(s, __float_as_int(g_dinv[s] * g_dinv[d]));
}

// ---------------- conversions ------------------------------------------------
__device__ __forceinline__ void split_bf16(float v, __nv_bfloat16& h, __nv_bfloat16& l) {
    h = __float2bfloat16(v);
    l = __float2bfloat16(v - __bfloat162float(h));
}

// W1[k][n] (128x128) -> w1t[f][k]; W2[k][n] (128x64) -> w2t[f][k]
__global__ void convert_w_kernel(const float* __restrict__ W1,
                                 const float* __restrict__ W2) {
    int stride = gridDim.x * blockDim.x;
    for (int i = blockIdx.x * blockDim.x + threadIdx.x; i < FH * FIN; i += stride) {
        int f = i >> 7, k = i & 127;
        split_bf16(W1[(size_t)k * FH + f], g_w1thi[i], g_w1tlo[i]);
    }
    for (int i = blockIdx.x * blockDim.x + threadIdx.x; i < FO * FH; i += stride) {
        int f = i >> 7, k = i & 127;
        split_bf16(W2[(size_t)k * FO + f], g_w2thi[i], g_w2tlo[i]);
    }
}

// ---------------- MMA helper -------------------------------------------------
__device__ __forceinline__ void mma16816(float* c, const unsigned* a,
                                         unsigned b0, unsigned b1) {
    asm volatile(
        "mma.sync.aligned.m16n8k16.row.col.f32.bf16.bf16.f32 "
        "{%0,%1,%2,%3}, {%4,%5,%6,%7}, {%8,%9}, {%0,%1,%2,%3};"
        : "+f"(c[0]), "+f"(c[1]), "+f"(c[2]), "+f"(c[3])
        : "r"(a[0]), "r"(a[1]), "r"(a[2]), "r"(a[3]), "r"(b0), "r"(b1));
}

// ---------------- fused convert + GEMM (layer 1) -----------------------------
// Reads X fp32, splits to bf16 hi/lo in smem, then tensor-core GEMM.
// 64 nodes/block, 256 threads (8 warps cover 128 output features).
#define GPAD 68   // padded row stride in 32-bit words (64 pairs + 4 pad)
__global__ void gemm128_fused_kernel(const float2* __restrict__ X,
                                     const __nv_bfloat16* __restrict__ wthi,
                                     const __nv_bfloat16* __restrict__ wtlo,
                                     float* __restrict__ H, int n) {
    __shared__ unsigned shi[64 * GPAD];
    __shared__ unsigned slo[64 * GPAD];
    const int tid = threadIdx.x;
    const int warp = tid >> 5, lane = tid & 31;
    const int g = lane >> 2, tg = lane & 3;
    const int f0 = warp * 16;
    const int node0 = blockIdx.x * 64;

    // stage + convert: 64 nodes x 64 k-pairs
#pragma unroll 4
    for (int it = 0; it < 16; it++) {
        int i = tid + 256 * it;              // 0..4095
        int nl = i >> 6, kp = i & 63;
        int gn = node0 + nl;
        float2 v = (gn < n) ? X[(size_t)gn * 64 + kp] : make_float2(0.f, 0.f);
        __nv_bfloat162 Hh, Ll;
        split_bf16(v.x, Hh.x, Ll.x);
        split_bf16(v.y, Hh.y, Ll.y);
        shi[nl * GPAD + kp] = *(unsigned*)&Hh;
        slo[nl * GPAD + kp] = *(unsigned*)&Ll;
    }

    // preload full-K weight fragments (loop-invariant)
    unsigned ahi[8][4], alo[8][4];
#pragma unroll
    for (int ks = 0; ks < 8; ks++) {
        int k0 = ks * 16 + tg * 2;
        ahi[ks][0] = *(const unsigned*)(wthi + (size_t)(f0 + g) * 128 + k0);
        ahi[ks][1] = *(const unsigned*)(wthi + (size_t)(f0 + 8 + g) * 128 + k0);
        ahi[ks][2] = *(const unsigned*)(wthi + (size_t)(f0 + g) * 128 + k0 + 8);
        ahi[ks][3] = *(const unsigned*)(wthi + (size_t)(f0 + 8 + g) * 128 + k0 + 8);
        alo[ks][0] = *(const unsigned*)(wtlo + (size_t)(f0 + g) * 128 + k0);
        alo[ks][1] = *(const unsigned*)(wtlo + (size_t)(f0 + 8 + g) * 128 + k0);
        alo[ks][2] = *(const unsigned*)(wtlo + (size_t)(f0 + g) * 128 + k0 + 8);
        alo[ks][3] = *(const unsigned*)(wtlo + (size_t)(f0 + 8 + g) * 128 + k0 + 8);
    }
    __syncthreads();

#pragma unroll 1
    for (int t = 0; t < 8; t++) {
        int nrow = t * 8 + g;                // local node for B fragment
        float c[4] = {0.f, 0.f, 0.f, 0.f};
#pragma unroll
        for (int ks = 0; ks < 8; ks++) {
            unsigned bh0 = shi[nrow * GPAD + ks * 8 + tg];
            unsigned bh1 = shi[nrow * GPAD + ks * 8 + 4 + tg];
            unsigned bl0 = slo[nrow * GPAD + ks * 8 + tg];
            unsigned bl1 = slo[nrow * GPAD + ks * 8 + 4 + tg];
            mma16816(c, ahi[ks], bh0, bh1);
            mma16816(c, ahi[ks], bl0, bl1);
            mma16816(c, alo[ks], bh0, bh1);
        }
        int n0 = node0 + t * 8;
        int nc0 = n0 + tg * 2, nc1 = nc0 + 1;
        if (nc0 < n) {
            H[(size_t)nc0 * FH + f0 + g]     = c[0];
            H[(size_t)nc0 * FH + f0 + 8 + g] = c[2];
        }
        if (nc1 < n) {
            H[(size_t)nc1 * FH + f0 + g]     = c[1];
            H[(size_t)nc1 * FH + f0 + 8 + g] = c[3];
        }
    }
}

// ---------------- layer-2 GEMM (bf16 hi/lo input from gmem) ------------------
template <int NF, int TPB>
__global__ void gemm_bf16_kernel(const __nv_bfloat16* __restrict__ xhi,
                                 const __nv_bfloat16* __restrict__ xlo,
                                 const __nv_bfloat16* __restrict__ wthi,
                                 const __nv_bfloat16* __restrict__ wtlo,
                                 float* __restrict__ H, int n) {
    const int warp = threadIdx.x >> 5, lane = threadIdx.x & 31;
    const int g = lane >> 2, tg = lane & 3;
    const int f0 = warp * 16;

    unsigned ahi[8][4], alo[8][4];
#pragma unroll
    for (int ks = 0; ks < 8; ks++) {
        int k0 = ks * 16 + tg * 2;
        ahi[ks][0] = *(const unsigned*)(wthi + (size_t)(f0 + g) * 128 + k0);
        ahi[ks][1] = *(const unsigned*)(wthi + (size_t)(f0 + 8 + g) * 128 + k0);
        ahi[ks][2] = *(const unsigned*)(wthi + (size_t)(f0 + g) * 128 + k0 + 8);
        ahi[ks][3] = *(const unsigned*)(wthi + (size_t)(f0 + 8 + g) * 128 + k0 + 8);
        alo[ks][0] = *(const unsigned*)(wtlo + (size_t)(f0 + g) * 128 + k0);
        alo[ks][1] = *(const unsigned*)(wtlo + (size_t)(f0 + 8 + g) * 128 + k0);
        alo[ks][2] = *(const unsigned*)(wtlo + (size_t)(f0 + g) * 128 + k0 + 8);
        alo[ks][3] = *(const unsigned*)(wtlo + (size_t)(f0 + 8 + g) * 128 + k0 + 8);
    }

    const int tile0 = blockIdx.x * TPB;
#pragma unroll 1
    for (int t = 0; t < TPB; t++) {
        int n0 = (tile0 + t) * 8;
        if (n0 >= n) break;
        int node = n0 + g;
        bool v = node < n;
        const unsigned* xh = (const unsigned*)(xhi + (size_t)node * 128);
        const unsigned* xl = (const unsigned*)(xlo + (size_t)node * 128);
        float c[4] = {0.f, 0.f, 0.f, 0.f};
#pragma unroll
        for (int ks = 0; ks < 8; ks++) {
            unsigned bh0 = v ? xh[ks * 8 + tg]     : 0u;
            unsigned bh1 = v ? xh[ks * 8 + 4 + tg] : 0u;
            unsigned bl0 = v ? xl[ks * 8 + tg]     : 0u;
            unsigned bl1 = v ? xl[ks * 8 + 4 + tg] : 0u;
            mma16816(c, ahi[ks], bh0, bh1);
            mma16816(c, ahi[ks], bl0, bl1);
            mma16816(c, alo[ks], bh0, bh1);
        }
        int nc0 = n0 + tg * 2, nc1 = nc0 + 1;
        if (nc0 < n) {
            H[(size_t)nc0 * NF + f0 + g]     = c[0];
            H[(size_t)nc0 * NF + f0 + 8 + g] = c[2];
        }
        if (nc1 < n) {
            H[(size_t)nc1 * NF + f0 + g]     = c[1];
            H[(size_t)nc1 * NF + f0 + 8 + g] = c[3];
        }
    }
}

// ---------------- gather aggregation (packed edges, unroll-2) ----------------
// Layer 1: out = relu(b + dinv^2*h + sum w*h[src]); writes bf16 hi/lo split.
__global__ void agg128_kernel(const float4* __restrict__ h,
                              const float4* __restrict__ bias,
                              __nv_bfloat162* __restrict__ ahi,
                              __nv_bfloat162* __restrict__ alo, int n) {
    int gid = blockIdx.x * blockDim.x + threadIdx.x;
    int node = gid >> 5, lane = gid & 31;
    if (node >= n) return;
    float di = g_dinv[node];
    float s2 = di * di;
    float4 v = h[(size_t)node * 32 + lane];
    float4 a0, a1;
    a0.x = v.x * s2; a0.y = v.y * s2; a0.z = v.z * s2; a0.w = v.w * s2;
    a1.x = 0.f; a1.y = 0.f; a1.z = 0.f; a1.w = 0.f;
    int b = g_start[node];
    int e = b + g_cnt[node];
    int j = b;
    for (; j + 2 <= e; j += 2) {
        int2 e0 = g_edge[j];
        int2 e1 = g_edge[j + 1];
        float4 u0 = h[(size_t)e0.x * 32 + lane];
        float4 u1 = h[(size_t)e1.x * 32 + lane];
        float w0 = __int_as_float(e0.y), w1 = __int_as_float(e1.y);
        a0.x += u0.x * w0; a0.y += u0.y * w0; a0.z += u0.z * w0; a0.w += u0.w * w0;
        a1.x += u1.x * w1; a1.y += u1.y * w1; a1.z += u1.z * w1; a1.w += u1.w * w1;
    }
    if (j < e) {
        int2 e0 = g_edge[j];
        float4 u0 = h[(size_t)e0.x * 32 + lane];
        float w0 = __int_as_float(e0.y);
        a0.x += u0.x * w0; a0.y += u0.y * w0; a0.z += u0.z * w0; a0.w += u0.w * w0;
    }
    float4 bv = bias[lane];
    float4 acc;
    acc.x = fmaxf(a0.x + a1.x + bv.x, 0.0f);
    acc.y = fmaxf(a0.y + a1.y + bv.y, 0.0f);
    acc.z = fmaxf(a0.z + a1.z + bv.z, 0.0f);
    acc.w = fmaxf(a0.w + a1.w + bv.w, 0.0f);
    __nv_bfloat162 H0, L0, H1, L1;
    split_bf16(acc.x, H0.x, L0.x);
    split_bf16(acc.y, H0.y, L0.y);
    split_bf16(acc.z, H1.x, L1.x);
    split_bf16(acc.w, H1.y, L1.y);
    size_t o = (size_t)node * 64 + lane * 2;
    ahi[o] = H0; ahi[o + 1] = H1;
    alo[o] = L0; alo[o + 1] = L1;
}

// Layer 2: out = b + dinv^2*h + sum w*h[src]  (fp32 out).
__global__ void agg64_kernel(const float2* __restrict__ h,
                             const float2* __restrict__ bias,
                             float2* __restrict__ out, int n) {
    int gid = blockIdx.x * blockDim.x + threadIdx.x;
    int node = gid >> 5, lane = gid & 31;
    if (node >= n) return;
    float di = g_dinv[node];
    float s2 = di * di;
    float2 v = h[(size_t)node * 32 + lane];
    float2 a0, a1;
    a0.x = v.x * s2; a0.y = v.y * s2;
    a1.x = 0.f; a1.y = 0.f;
    int b = g_start[node];
    int e = b + g_cnt[node];
    int j = b;
    for (; j + 2 <= e; j += 2) {
        int2 e0 = g_edge[j];
        int2 e1 = g_edge[j + 1];
        float2 u0 = h[(size_t)e0.x * 32 + lane];
        float2 u1 = h[(size_t)e1.x * 32 + lane];
        float w0 = __int_as_float(e0.y), w1 = __int_as_float(e1.y);
        a0.x += u0.x * w0; a0.y += u0.y * w0;
        a1.x += u1.x * w1; a1.y += u1.y * w1;
    }
    if (j < e) {
        int2 e0 = g_edge[j];
        float2 u0 = h[(size_t)e0.x * 32 + lane];
        float w0 = __int_as_float(e0.y);
        a0.x += u0.x * w0; a0.y += u0.y * w0;
    }
    float2 bv = bias[lane];
    float2 acc;
    acc.x = a0.x + a1.x + bv.x;
    acc.y = a0.y + a1.y + bv.y;
    out[(size_t)node * 32 + lane] = acc;
}

// ---------------- launch ------------------------------------------------------
extern "C" void kernel_launch(void* const* d_in, const int* in_sizes, int n_in,
                              void* d_out, int out_size) {
    const float* x  = (const float*)d_in[0];
    const void*  ei = d_in[1];
    const float* W1 = (const float*)d_in[2];
    const float* b1 = (const float*)d_in[3];
    const float* W2 = (const float*)d_in[4];
    const float* b2 = (const float*)d_in[5];
    float* out = (float*)d_out;

    const int n = in_sizes[0] / FIN;   // 100000
    const int E = in_sizes[1] / 2;     // 600000

    float *p_h1, *p_h2;
    __nv_bfloat16 *p_a1hi, *p_a1lo, *p_w1thi, *p_w1tlo, *p_w2thi, *p_w2tlo;
    cudaGetSymbolAddress((void**)&p_h1, g_h1);
    cudaGetSymbolAddress((void**)&p_h2, g_h2);
    cudaGetSymbolAddress((void**)&p_a1hi, g_a1hi);
    cudaGetSymbolAddress((void**)&p_a1lo, g_a1lo);
    cudaGetSymbolAddress((void**)&p_w1thi, g_w1thi);
    cudaGetSymbolAddress((void**)&p_w1tlo, g_w1tlo);
    cudaGetSymbolAddress((void**)&p_w2thi, g_w2thi);
    cudaGetSymbolAddress((void**)&p_w2tlo, g_w2tlo);

    static cudaStream_t s2 = nullptr;
    static cudaEvent_t evFork = nullptr, evJoin = nullptr;
    if (!s2) {
        cudaStreamCreate(&s2);
        cudaEventCreateWithFlags(&evFork, cudaEventDisableTiming);
        cudaEventCreateWithFlags(&evJoin, cudaEventDisableTiming);
    }

    // (1) main: weight convert
    convert_w_kernel<<<96, 256>>>(W1, W2);

    // fork CSR build to s2
    cudaEventRecord(evFork, 0);
    cudaStreamWaitEvent(s2, evFork, 0);
    // (2)(3) s2
    detect_dtype_kernel<<<1, 32, 0, s2>>>((const unsigned int*)ei);
    init_kernel<<<(n + 255) / 256, 256, 0, s2>>>(n);

    // (4) main: fused convert + layer-1 GEMM  (profiled launch)
    gemm128_fused_kernel<<<(n + 63) / 64, 256>>>(
        (const float2*)x, p_w1thi, p_w1tlo, p_h1, n);

    // (5..7) s2: rest of CSR build
    count_kernel<<<(E + 255) / 256, 256, 0, s2>>>(ei, E);
    prep_kernel<<<(n + 255) / 256, 256, 0, s2>>>(n);
    fill_kernel<<<(E + 255) / 256, 256, 0, s2>>>(ei, E);
    cudaEventRecord(evJoin, s2);

    // join: aggregation needs CSR + h1
    cudaStreamWaitEvent(0, evJoin, 0);
    agg128_kernel<<<(n * 32 + 255) / 256, 256>>>(
        (const float4*)p_h1, (const float4*)b1,
        (__nv_bfloat162*)p_a1hi, (__nv_bfloat162*)p_a1lo, n);

    // layer 2
    gemm_bf16_kernel<64, 16><<<(n + 127) / 128, 128>>>(
        p_a1hi, p_a1lo, p_w2thi, p_w2tlo, p_h2, n);
    agg64_kernel<<<(n * 32 + 255) / 256, 256>>>(
        (const float2*)p_h2, (const float2*)b2, (float2*)out, n);
}